// round 11
// baseline (speedup 1.0000x reference)
#include <cuda_runtime.h>
#include <cstdint>
#include <math.h>

#define FULL 0xffffffffu

// ---------------------------------------------------------------------------
// Threefry-2x32 (20 rounds), matching jax._src.prng exactly.
// ---------------------------------------------------------------------------
__host__ __device__ __forceinline__ constexpr unsigned rotl_c(unsigned x, int r) {
    return (x << r) | (x >> (32 - r));
}

struct K2 { unsigned a, b; };

__host__ __device__ constexpr K2 tf_c(unsigned k0, unsigned k1, unsigned x0, unsigned x1) {
    unsigned ks2 = k0 ^ k1 ^ 0x1BD11BDAu;
    x0 += k0; x1 += k1;
    x0 += x1; x1 = rotl_c(x1, 13); x1 ^= x0;
    x0 += x1; x1 = rotl_c(x1, 15); x1 ^= x0;
    x0 += x1; x1 = rotl_c(x1, 26); x1 ^= x0;
    x0 += x1; x1 = rotl_c(x1, 6);  x1 ^= x0;
    x0 += k1; x1 += ks2 + 1u;
    x0 += x1; x1 = rotl_c(x1, 17); x1 ^= x0;
    x0 += x1; x1 = rotl_c(x1, 29); x1 ^= x0;
    x0 += x1; x1 = rotl_c(x1, 16); x1 ^= x0;
    x0 += x1; x1 = rotl_c(x1, 24); x1 ^= x0;
    x0 += ks2; x1 += k0 + 2u;
    x0 += x1; x1 = rotl_c(x1, 13); x1 ^= x0;
    x0 += x1; x1 = rotl_c(x1, 15); x1 ^= x0;
    x0 += x1; x1 = rotl_c(x1, 26); x1 ^= x0;
    x0 += x1; x1 = rotl_c(x1, 6);  x1 ^= x0;
    x0 += k0; x1 += k1 + 3u;
    x0 += x1; x1 = rotl_c(x1, 17); x1 ^= x0;
    x0 += x1; x1 = rotl_c(x1, 29); x1 ^= x0;
    x0 += x1; x1 = rotl_c(x1, 16); x1 ^= x0;
    x0 += x1; x1 = rotl_c(x1, 24); x1 ^= x0;
    x0 += k1; x1 += ks2 + 4u;
    x0 += x1; x1 = rotl_c(x1, 13); x1 ^= x0;
    x0 += x1; x1 = rotl_c(x1, 15); x1 ^= x0;
    x0 += x1; x1 = rotl_c(x1, 26); x1 ^= x0;
    x0 += x1; x1 = rotl_c(x1, 6);  x1 ^= x0;
    x0 += ks2; x1 += k0 + 5u;
    return K2{x0, x1};
}

// jax.random.key(42); partitionable split: key i = threefry(key, (0, i))
constexpr K2 KR = tf_c(0u, 42u, 0u, 0u);  // rr key
constexpr K2 KG = tf_c(0u, 42u, 0u, 1u);  // gg key

__device__ __forceinline__ unsigned tf_bits(unsigned k0, unsigned k1, unsigned f) {
    K2 o = tf_c(k0, k1, 0u, f);
    return o.a ^ o.b;
}

// ---------------------------------------------------------------------------
// XLA:CPU vectorized exp (Cephes) WITH x86 FMA contraction (FPOpFusion::Fast).
// Boundary-critical: used ONLY for the sigmoid that positions the means.
// ---------------------------------------------------------------------------
__device__ __forceinline__ float exp_xla_cpu_fma(float a) {
    const float kLog2e = 1.44269504088896341f;
    const float kC1    = 0.693359375f;
    const float kC2    = -2.12194440e-4f;
    float n = floorf(fmaf(a, kLog2e, 0.5f));
    float x = fmaf(-n, kC1, a);
    x = fmaf(-n, kC2, x);
    float z = __fmul_rn(x, x);
    float y = fmaf(x, 1.9875691500E-4f, 1.3981999507E-3f);
    y = fmaf(y, x, 8.3334519073E-3f);
    y = fmaf(y, x, 4.1665795894E-2f);
    y = fmaf(y, x, 1.6666665459E-1f);
    y = fmaf(y, x, 5.0000001201E-1f);
    y = fmaf(y, z, x);
    y = __fadd_rn(y, 1.0f);
    float pow2n = __int_as_float(((int)n + 127) << 23);
    return __fmul_rn(y, pow2n);
}

__device__ __forceinline__ float logistic_f(float x) {
    float e = exp_xla_cpu_fma(-x);
    return __fdiv_rn(1.0f, __fadd_rn(1.0f, e));
}

constexpr float ONE_MINUS_EPS = (float)(1.0 - 1e-6);
// IN_NUM=65536, OUT_NUM=65536, K=4, n=24, REGION=128, EMB=128

__global__ __launch_bounds__(256) void hyper_kernel(
    const float* __restrict__ params,
    const float* __restrict__ x,
    float* __restrict__ out)
{
    const int lane = threadIdx.x & 31;
    const int c = blockIdx.x * 8 + (threadIdx.x >> 5);   // one warp per row

    // ---- per-k (lanes 0..3): mean (EXACT path), sigma-reciprocal, value ----
    float mean = 0.f, rinv = 0.f, val = 0.f;
    if (lane < 4) {
        const float* pr = params + ((size_t)c * 4 + lane) * 3;
        float p0 = pr[0], p1 = pr[1], p2 = pr[2];
        mean = __fmul_rn(logistic_f(p0), 65535.0f);
        // softplus (smooth path — cannot flip integers)
        float z = p1 + 2.0f;
        float sp = fmaxf(z, 0.0f) + log1pf(expf(-fabsf(z)));
        float sigma = __fmul_rn(__fmul_rn(__fadd_rn(sp, 1e-6f), 65536.0f), 0.2f);
        rinv = __fdividef(-0.5f, 1e-6f + sigma);   // premultiplied -0.5/(eps+sig)
        val = p2;
    }
    float mk[4], rk[4], vk[4];
#pragma unroll
    for (int k = 0; k < 4; k++) {
        mk[k] = __shfl_sync(FULL, mean, k);
        rk[k] = __shfl_sync(FULL, rinv, k);
        vk[k] = __shfl_sync(FULL, val, k);
    }

    // ---- per-point (lane j): unified single threefry ----------------------
    const int k6 = lane / 6;                 // 4..5 for lanes>=24 (discarded)
    const int t  = lane - k6 * 6;
    const float m = __shfl_sync(FULL, mean, k6);   // lanes>=24 read 0

    const bool isg = (t >= 4);
    unsigned key0 = isg ? KG.a : KR.a;
    unsigned key1 = isg ? KG.b : KR.b;
    unsigned flat = (unsigned)c * 8u + (unsigned)k6 * 2u + (unsigned)(t & 1);
    unsigned bits = tf_bits(key0, key1, flat);
    float u  = __uint_as_float((bits >> 9) | 0x3f800000u) - 1.0f;
    float rr = __fmul_rn(u, ONE_MINUS_EPS);

    // region bounds (exact per reference)
    float mr = rintf(m);
    float lo = mr - 64.0f;
    lo = (lo < 0.0f) ? 0.0f : lo;
    lo = (mr + 64.0f > 65536.0f) ? 65408.0f : lo;  // in_num - REGION

    float fv = (t == 0) ? floorf(m)
             : (t == 1) ? ceilf(m)
             : (t <  4) ? floorf(__fadd_rn(__fmul_rn(rr, 128.0f), lo))
                        : floorf(__fmul_rn(rr, 65536.0f));
    const int myint = (lane < 24) ? (int)fv : (-1 - lane);  // unique sentinels
    const float mypt = fv;

    // ---- duplicate detection in one instruction ---------------------------
    unsigned mmask = __match_any_sync(FULL, myint);
    const bool dup = (mmask & ((1u << lane) - 1u)) != 0u;
    const bool act0 = (lane < 24) && !dup;

    // ---- Gaussian props, normalize, mix ------------------------------------
    float v = 0.f;
    float pk[4];
#pragma unroll
    for (int k = 0; k < 4; k++) {
        float d = mypt - mk[k];
        float e = __fmul_rn(__fmul_rn(d, d), rk[k]);
        pk[k] = act0 ? __expf(e) : 0.f;
    }
#pragma unroll
    for (int k = 0; k < 4; k++) {
        float s = pk[k];
#pragma unroll
        for (int off = 16; off; off >>= 1)
            s += __shfl_xor_sync(FULL, s, off);
        float w = __fdividef(vk[k], s);     // fast div; smooth path
        v = fmaf(pk[k], w, v);
    }
    if (myint == c) v = 0.f;                // rows == cols -> zero

    // ---- one-time branch-free compaction: lane i <- i-th active (v, idx) --
    unsigned amask = __ballot_sync(FULL, fabsf(v) > 1e-12f);
    const int nact = __popc(amask);
    int src = __fns(amask, 0, lane + 1);    // i-th set bit (garbage if none)
    src &= 31;                              // keep shuffle well-defined
    const float cv = __shfl_sync(FULL, v, src);
    const int   ci = __shfl_sync(FULL, myint, src);

    // ---- 2-wide gather loop, no internal branches -------------------------
    const float4* __restrict__ xb = (const float4*)x + lane;
    float4 a0 = make_float4(0.f, 0.f, 0.f, 0.f);
    float4 a1 = make_float4(0.f, 0.f, 0.f, 0.f);
    int j = 0;
    for (; j + 1 < nact; j += 2) {
        float w0 = __shfl_sync(FULL, cv, j);
        float w1 = __shfl_sync(FULL, cv, j + 1);
        int   i0 = __shfl_sync(FULL, ci, j);
        int   i1 = __shfl_sync(FULL, ci, j + 1);
        float4 q0 = __ldg(xb + ((unsigned)i0 << 5));
        float4 q1 = __ldg(xb + ((unsigned)i1 << 5));
        a0.x = fmaf(w0, q0.x, a0.x); a0.y = fmaf(w0, q0.y, a0.y);
        a0.z = fmaf(w0, q0.z, a0.z); a0.w = fmaf(w0, q0.w, a0.w);
        a1.x = fmaf(w1, q1.x, a1.x); a1.y = fmaf(w1, q1.y, a1.y);
        a1.z = fmaf(w1, q1.z, a1.z); a1.w = fmaf(w1, q1.w, a1.w);
    }
    if (j < nact) {                          // single tail
        float w0 = __shfl_sync(FULL, cv, j);
        int   i0 = __shfl_sync(FULL, ci, j);
        float4 q0 = __ldg(xb + ((unsigned)i0 << 5));
        a0.x = fmaf(w0, q0.x, a0.x); a0.y = fmaf(w0, q0.y, a0.y);
        a0.z = fmaf(w0, q0.z, a0.z); a0.w = fmaf(w0, q0.w, a0.w);
    }
    a0.x += a1.x; a0.y += a1.y; a0.z += a1.z; a0.w += a1.w;
    ((float4*)out)[(unsigned)c * 32u + (unsigned)lane] = a0;
}

extern "C" void kernel_launch(void* const* d_in, const int* in_sizes, int n_in,
                              void* d_out, int out_size)
{
    const float* params = (const float*)d_in[0];   // (262144, 3) f32
    const float* x      = (const float*)d_in[1];   // (65536, 128) f32
    float* out          = (float*)d_out;           // (65536, 128) f32
    (void)in_sizes; (void)n_in; (void)out_size;
    hyper_kernel<<<65536 / 8, 256>>>(params, x, out);
}

// round 12
// speedup vs baseline: 1.0383x; 1.0383x over previous
#include <cuda_runtime.h>
#include <cstdint>
#include <math.h>

#define FULL 0xffffffffu

// ---------------------------------------------------------------------------
// Threefry-2x32 (20 rounds), matching jax._src.prng exactly.
// ---------------------------------------------------------------------------
__host__ __device__ __forceinline__ constexpr unsigned rotl_c(unsigned x, int r) {
    return (x << r) | (x >> (32 - r));
}

struct K2 { unsigned a, b; };

__host__ __device__ constexpr K2 tf_c(unsigned k0, unsigned k1, unsigned x0, unsigned x1) {
    unsigned ks2 = k0 ^ k1 ^ 0x1BD11BDAu;
    x0 += k0; x1 += k1;
    x0 += x1; x1 = rotl_c(x1, 13); x1 ^= x0;
    x0 += x1; x1 = rotl_c(x1, 15); x1 ^= x0;
    x0 += x1; x1 = rotl_c(x1, 26); x1 ^= x0;
    x0 += x1; x1 = rotl_c(x1, 6);  x1 ^= x0;
    x0 += k1; x1 += ks2 + 1u;
    x0 += x1; x1 = rotl_c(x1, 17); x1 ^= x0;
    x0 += x1; x1 = rotl_c(x1, 29); x1 ^= x0;
    x0 += x1; x1 = rotl_c(x1, 16); x1 ^= x0;
    x0 += x1; x1 = rotl_c(x1, 24); x1 ^= x0;
    x0 += ks2; x1 += k0 + 2u;
    x0 += x1; x1 = rotl_c(x1, 13); x1 ^= x0;
    x0 += x1; x1 = rotl_c(x1, 15); x1 ^= x0;
    x0 += x1; x1 = rotl_c(x1, 26); x1 ^= x0;
    x0 += x1; x1 = rotl_c(x1, 6);  x1 ^= x0;
    x0 += k0; x1 += k1 + 3u;
    x0 += x1; x1 = rotl_c(x1, 17); x1 ^= x0;
    x0 += x1; x1 = rotl_c(x1, 29); x1 ^= x0;
    x0 += x1; x1 = rotl_c(x1, 16); x1 ^= x0;
    x0 += x1; x1 = rotl_c(x1, 24); x1 ^= x0;
    x0 += k1; x1 += ks2 + 4u;
    x0 += x1; x1 = rotl_c(x1, 13); x1 ^= x0;
    x0 += x1; x1 = rotl_c(x1, 15); x1 ^= x0;
    x0 += x1; x1 = rotl_c(x1, 26); x1 ^= x0;
    x0 += x1; x1 = rotl_c(x1, 6);  x1 ^= x0;
    x0 += ks2; x1 += k0 + 5u;
    return K2{x0, x1};
}

// jax.random.key(42); partitionable split: key i = threefry(key, (0, i))
constexpr K2 KR = tf_c(0u, 42u, 0u, 0u);  // rr key
constexpr K2 KG = tf_c(0u, 42u, 0u, 1u);  // gg key

__device__ __forceinline__ unsigned tf_bits(unsigned k0, unsigned k1, unsigned f) {
    K2 o = tf_c(k0, k1, 0u, f);
    return o.a ^ o.b;
}

// ---------------------------------------------------------------------------
// XLA:CPU vectorized exp (Cephes) WITH x86 FMA contraction (FPOpFusion::Fast).
// Boundary-critical: used ONLY for the sigmoid that positions the means.
// ---------------------------------------------------------------------------
__device__ __forceinline__ float exp_xla_cpu_fma(float a) {
    const float kLog2e = 1.44269504088896341f;
    const float kC1    = 0.693359375f;
    const float kC2    = -2.12194440e-4f;
    float n = floorf(fmaf(a, kLog2e, 0.5f));
    float x = fmaf(-n, kC1, a);
    x = fmaf(-n, kC2, x);
    float z = __fmul_rn(x, x);
    float y = fmaf(x, 1.9875691500E-4f, 1.3981999507E-3f);
    y = fmaf(y, x, 8.3334519073E-3f);
    y = fmaf(y, x, 4.1665795894E-2f);
    y = fmaf(y, x, 1.6666665459E-1f);
    y = fmaf(y, x, 5.0000001201E-1f);
    y = fmaf(y, z, x);
    y = __fadd_rn(y, 1.0f);
    float pow2n = __int_as_float(((int)n + 127) << 23);
    return __fmul_rn(y, pow2n);
}

__device__ __forceinline__ float logistic_f(float x) {
    float e = exp_xla_cpu_fma(-x);
    return __fdiv_rn(1.0f, __fadd_rn(1.0f, e));
}

constexpr float ONE_MINUS_EPS = (float)(1.0 - 1e-6);
// IN_NUM=65536, OUT_NUM=65536, K=4, n=24, REGION=128, EMB=128

__global__ __launch_bounds__(256) void hyper_kernel(
    const float* __restrict__ params,
    const float* __restrict__ x,
    float* __restrict__ out)
{
    const int lane = threadIdx.x & 31;
    const int c = blockIdx.x * 8 + (threadIdx.x >> 5);   // one warp per row

    // ---- per-k (lanes 0..3): mean (EXACT path), sigma-reciprocal, value ----
    float mean = 0.f, rinv = 0.f, val = 0.f;
    if (lane < 4) {
        const float* pr = params + ((size_t)c * 4 + lane) * 3;
        float p0 = pr[0], p1 = pr[1], p2 = pr[2];
        mean = __fmul_rn(logistic_f(p0), 65535.0f);
        // softplus (smooth path — cannot flip integers)
        float z = p1 + 2.0f;
        float sp = fmaxf(z, 0.0f) + log1pf(expf(-fabsf(z)));
        float sigma = __fmul_rn(__fmul_rn(__fadd_rn(sp, 1e-6f), 65536.0f), 0.2f);
        rinv = __fdividef(-0.5f, 1e-6f + sigma);   // premultiplied -0.5/(eps+sig)
        val = p2;
    }
    float mk[4], rk[4], vk[4];
#pragma unroll
    for (int k = 0; k < 4; k++) {
        mk[k] = __shfl_sync(FULL, mean, k);
        rk[k] = __shfl_sync(FULL, rinv, k);
        vk[k] = __shfl_sync(FULL, val, k);
    }

    // ---- per-point (lane j): unified single threefry ----------------------
    const int k6 = lane / 6;                 // 4..5 for lanes>=24 (discarded)
    const int t  = lane - k6 * 6;
    const float m = __shfl_sync(FULL, mean, k6);   // lanes>=24 read 0

    const bool isg = (t >= 4);
    unsigned key0 = isg ? KG.a : KR.a;
    unsigned key1 = isg ? KG.b : KR.b;
    unsigned flat = (unsigned)c * 8u + (unsigned)k6 * 2u + (unsigned)(t & 1);
    unsigned bits = tf_bits(key0, key1, flat);
    float u  = __uint_as_float((bits >> 9) | 0x3f800000u) - 1.0f;
    float rr = __fmul_rn(u, ONE_MINUS_EPS);

    // region bounds (exact per reference)
    float mr = rintf(m);
    float lo = mr - 64.0f;
    lo = (lo < 0.0f) ? 0.0f : lo;
    lo = (mr + 64.0f > 65536.0f) ? 65408.0f : lo;  // in_num - REGION

    float fv = (t == 0) ? floorf(m)
             : (t == 1) ? ceilf(m)
             : (t <  4) ? floorf(__fadd_rn(__fmul_rn(rr, 128.0f), lo))
                        : floorf(__fmul_rn(rr, 65536.0f));
    const int myint = (lane < 24) ? (int)fv : (-1 - lane);  // unique sentinels
    const float mypt = fv;

    // ---- duplicate detection in one instruction ---------------------------
    unsigned mmask = __match_any_sync(FULL, myint);
    const bool dup = (mmask & ((1u << lane) - 1u)) != 0u;
    const bool act0 = (lane < 24) && !dup;

    // ---- Gaussian props, normalize, mix ------------------------------------
    float v = 0.f;
    float pk[4];
#pragma unroll
    for (int k = 0; k < 4; k++) {
        float d = mypt - mk[k];
        float e = __fmul_rn(__fmul_rn(d, d), rk[k]);
        pk[k] = act0 ? __expf(e) : 0.f;
    }
#pragma unroll
    for (int k = 0; k < 4; k++) {
        float s = pk[k];
#pragma unroll
        for (int off = 16; off; off >>= 1)
            s += __shfl_xor_sync(FULL, s, off);
        float w = __fdividef(vk[k], s);     // fast div; smooth path
        v = fmaf(pk[k], w, v);
    }
    if (myint == c) v = 0.f;                // rows == cols -> zero

    // ---- one-time branch-free compaction: lane i <- i-th active (v, idx) --
    unsigned amask = __ballot_sync(FULL, fabsf(v) > 1e-12f);
    const int nact = __popc(amask);
    int src = __fns(amask, 0, lane + 1);    // i-th set bit (garbage if none)
    src &= 31;                              // keep shuffle well-defined
    const float cv = __shfl_sync(FULL, v, src);
    const int   ci = __shfl_sync(FULL, myint, src);

    // ---- 2-wide gather loop, no internal branches -------------------------
    const float4* __restrict__ xb = (const float4*)x + lane;
    float4 a0 = make_float4(0.f, 0.f, 0.f, 0.f);
    float4 a1 = make_float4(0.f, 0.f, 0.f, 0.f);
    int j = 0;
    for (; j + 1 < nact; j += 2) {
        float w0 = __shfl_sync(FULL, cv, j);
        float w1 = __shfl_sync(FULL, cv, j + 1);
        int   i0 = __shfl_sync(FULL, ci, j);
        int   i1 = __shfl_sync(FULL, ci, j + 1);
        float4 q0 = __ldg(xb + ((unsigned)i0 << 5));
        float4 q1 = __ldg(xb + ((unsigned)i1 << 5));
        a0.x = fmaf(w0, q0.x, a0.x); a0.y = fmaf(w0, q0.y, a0.y);
        a0.z = fmaf(w0, q0.z, a0.z); a0.w = fmaf(w0, q0.w, a0.w);
        a1.x = fmaf(w1, q1.x, a1.x); a1.y = fmaf(w1, q1.y, a1.y);
        a1.z = fmaf(w1, q1.z, a1.z); a1.w = fmaf(w1, q1.w, a1.w);
    }
    if (j < nact) {                          // single tail
        float w0 = __shfl_sync(FULL, cv, j);
        int   i0 = __shfl_sync(FULL, ci, j);
        float4 q0 = __ldg(xb + ((unsigned)i0 << 5));
        a0.x = fmaf(w0, q0.x, a0.x); a0.y = fmaf(w0, q0.y, a0.y);
        a0.z = fmaf(w0, q0.z, a0.z); a0.w = fmaf(w0, q0.w, a0.w);
    }
    a0.x += a1.x; a0.y += a1.y; a0.z += a1.z; a0.w += a1.w;
    ((float4*)out)[(unsigned)c * 32u + (unsigned)lane] = a0;
}

extern "C" void kernel_launch(void* const* d_in, const int* in_sizes, int n_in,
                              void* d_out, int out_size)
{
    const float* params = (const float*)d_in[0];   // (262144, 3) f32
    const float* x      = (const float*)d_in[1];   // (65536, 128) f32
    float* out          = (float*)d_out;           // (65536, 128) f32
    (void)in_sizes; (void)n_in; (void)out_size;
    hyper_kernel<<<65536 / 8, 256>>>(params, x, out);
}

// round 13
// speedup vs baseline: 1.0390x; 1.0007x over previous
#include <cuda_runtime.h>
#include <cstdint>
#include <math.h>

#define FULL 0xffffffffu

// ---------------------------------------------------------------------------
// Threefry-2x32 (20 rounds), matching jax._src.prng exactly.
// ---------------------------------------------------------------------------
__host__ __device__ __forceinline__ constexpr unsigned rotl_c(unsigned x, int r) {
    return (x << r) | (x >> (32 - r));
}

struct K2 { unsigned a, b; };

__host__ __device__ constexpr K2 tf_c(unsigned k0, unsigned k1, unsigned x0, unsigned x1) {
    unsigned ks2 = k0 ^ k1 ^ 0x1BD11BDAu;
    x0 += k0; x1 += k1;
    x0 += x1; x1 = rotl_c(x1, 13); x1 ^= x0;
    x0 += x1; x1 = rotl_c(x1, 15); x1 ^= x0;
    x0 += x1; x1 = rotl_c(x1, 26); x1 ^= x0;
    x0 += x1; x1 = rotl_c(x1, 6);  x1 ^= x0;
    x0 += k1; x1 += ks2 + 1u;
    x0 += x1; x1 = rotl_c(x1, 17); x1 ^= x0;
    x0 += x1; x1 = rotl_c(x1, 29); x1 ^= x0;
    x0 += x1; x1 = rotl_c(x1, 16); x1 ^= x0;
    x0 += x1; x1 = rotl_c(x1, 24); x1 ^= x0;
    x0 += ks2; x1 += k0 + 2u;
    x0 += x1; x1 = rotl_c(x1, 13); x1 ^= x0;
    x0 += x1; x1 = rotl_c(x1, 15); x1 ^= x0;
    x0 += x1; x1 = rotl_c(x1, 26); x1 ^= x0;
    x0 += x1; x1 = rotl_c(x1, 6);  x1 ^= x0;
    x0 += k0; x1 += k1 + 3u;
    x0 += x1; x1 = rotl_c(x1, 17); x1 ^= x0;
    x0 += x1; x1 = rotl_c(x1, 29); x1 ^= x0;
    x0 += x1; x1 = rotl_c(x1, 16); x1 ^= x0;
    x0 += x1; x1 = rotl_c(x1, 24); x1 ^= x0;
    x0 += k1; x1 += ks2 + 4u;
    x0 += x1; x1 = rotl_c(x1, 13); x1 ^= x0;
    x0 += x1; x1 = rotl_c(x1, 15); x1 ^= x0;
    x0 += x1; x1 = rotl_c(x1, 26); x1 ^= x0;
    x0 += x1; x1 = rotl_c(x1, 6);  x1 ^= x0;
    x0 += ks2; x1 += k0 + 5u;
    return K2{x0, x1};
}

// jax.random.key(42); partitionable split: key i = threefry(key, (0, i))
constexpr K2 KR = tf_c(0u, 42u, 0u, 0u);  // rr key
constexpr K2 KG = tf_c(0u, 42u, 0u, 1u);  // gg key

__device__ __forceinline__ unsigned tf_bits(unsigned k0, unsigned k1, unsigned f) {
    K2 o = tf_c(k0, k1, 0u, f);
    return o.a ^ o.b;
}

// ---------------------------------------------------------------------------
// XLA:CPU vectorized exp (Cephes) WITH x86 FMA contraction (FPOpFusion::Fast).
// Boundary-critical: used ONLY for the sigmoid that positions the means.
// ---------------------------------------------------------------------------
__device__ __forceinline__ float exp_xla_cpu_fma(float a) {
    const float kLog2e = 1.44269504088896341f;
    const float kC1    = 0.693359375f;
    const float kC2    = -2.12194440e-4f;
    float n = floorf(fmaf(a, kLog2e, 0.5f));
    float x = fmaf(-n, kC1, a);
    x = fmaf(-n, kC2, x);
    float z = __fmul_rn(x, x);
    float y = fmaf(x, 1.9875691500E-4f, 1.3981999507E-3f);
    y = fmaf(y, x, 8.3334519073E-3f);
    y = fmaf(y, x, 4.1665795894E-2f);
    y = fmaf(y, x, 1.6666665459E-1f);
    y = fmaf(y, x, 5.0000001201E-1f);
    y = fmaf(y, z, x);
    y = __fadd_rn(y, 1.0f);
    float pow2n = __int_as_float(((int)n + 127) << 23);
    return __fmul_rn(y, pow2n);
}

__device__ __forceinline__ float logistic_f(float x) {
    float e = exp_xla_cpu_fma(-x);
    return __fdiv_rn(1.0f, __fadd_rn(1.0f, e));
}

constexpr float ONE_MINUS_EPS = (float)(1.0 - 1e-6);
// IN_NUM=65536, OUT_NUM=65536, K=4, n=24, REGION=128, EMB=128

__global__ __launch_bounds__(256) void hyper_kernel(
    const float* __restrict__ params,
    const float* __restrict__ x,
    float* __restrict__ out)
{
    const int lane = threadIdx.x & 31;
    const int c = blockIdx.x * 8 + (threadIdx.x >> 5);   // one warp per row

    // ---- per-k (lanes 0..3): mean (EXACT path), sigma-reciprocal, value ----
    float mean = 0.f, rinv = 0.f, val = 0.f;
    if (lane < 4) {
        const float* pr = params + ((size_t)c * 4 + lane) * 3;
        float p0 = pr[0], p1 = pr[1], p2 = pr[2];
        mean = __fmul_rn(logistic_f(p0), 65535.0f);
        // softplus (smooth path — cannot flip integers)
        float z = p1 + 2.0f;
        float sp = fmaxf(z, 0.0f) + log1pf(expf(-fabsf(z)));
        float sigma = __fmul_rn(__fmul_rn(__fadd_rn(sp, 1e-6f), 65536.0f), 0.2f);
        rinv = __fdividef(-0.5f, 1e-6f + sigma);   // premultiplied -0.5/(eps+sig)
        val = p2;
    }
    float mk[4], rk[4], vk[4];
#pragma unroll
    for (int k = 0; k < 4; k++) {
        mk[k] = __shfl_sync(FULL, mean, k);
        rk[k] = __shfl_sync(FULL, rinv, k);
        vk[k] = __shfl_sync(FULL, val, k);
    }

    // ---- per-point (lane j): unified single threefry ----------------------
    const int k6 = lane / 6;                 // 4..5 for lanes>=24 (discarded)
    const int t  = lane - k6 * 6;
    const float m = __shfl_sync(FULL, mean, k6);   // lanes>=24 read 0

    const bool isg = (t >= 4);
    unsigned key0 = isg ? KG.a : KR.a;
    unsigned key1 = isg ? KG.b : KR.b;
    unsigned flat = (unsigned)c * 8u + (unsigned)k6 * 2u + (unsigned)(t & 1);
    unsigned bits = tf_bits(key0, key1, flat);
    float u  = __uint_as_float((bits >> 9) | 0x3f800000u) - 1.0f;
    float rr = __fmul_rn(u, ONE_MINUS_EPS);

    // region bounds (exact per reference)
    float mr = rintf(m);
    float lo = mr - 64.0f;
    lo = (lo < 0.0f) ? 0.0f : lo;
    lo = (mr + 64.0f > 65536.0f) ? 65408.0f : lo;  // in_num - REGION

    float fv = (t == 0) ? floorf(m)
             : (t == 1) ? ceilf(m)
             : (t <  4) ? floorf(__fadd_rn(__fmul_rn(rr, 128.0f), lo))
                        : floorf(__fmul_rn(rr, 65536.0f));
    const int myint = (lane < 24) ? (int)fv : (-1 - lane);  // unique sentinels
    const float mypt = fv;

    // ---- duplicate detection in one instruction ---------------------------
    unsigned mmask = __match_any_sync(FULL, myint);
    const bool dup = (mmask & ((1u << lane) - 1u)) != 0u;
    const bool act0 = (lane < 24) && !dup;

    // ---- Gaussian props, normalize, mix ------------------------------------
    float v = 0.f;
    float pk[4];
#pragma unroll
    for (int k = 0; k < 4; k++) {
        float d = mypt - mk[k];
        float e = __fmul_rn(__fmul_rn(d, d), rk[k]);
        pk[k] = act0 ? __expf(e) : 0.f;
    }
#pragma unroll
    for (int k = 0; k < 4; k++) {
        float s = pk[k];
#pragma unroll
        for (int off = 16; off; off >>= 1)
            s += __shfl_xor_sync(FULL, s, off);
        float w = __fdividef(vk[k], s);     // fast div; smooth path
        v = fmaf(pk[k], w, v);
    }
    if (myint == c) v = 0.f;                // rows == cols -> zero

    // ---- one-time branch-free compaction: lane i <- i-th active (v, idx) --
    unsigned amask = __ballot_sync(FULL, fabsf(v) > 1e-12f);
    const int nact = __popc(amask);
    int src = __fns(amask, 0, lane + 1);    // i-th set bit (garbage if none)
    src &= 31;                              // keep shuffle well-defined
    const float cv = __shfl_sync(FULL, v, src);
    const int   ci = __shfl_sync(FULL, myint, src);

    // ---- 2-wide gather loop, no internal branches -------------------------
    const float4* __restrict__ xb = (const float4*)x + lane;
    float4 a0 = make_float4(0.f, 0.f, 0.f, 0.f);
    float4 a1 = make_float4(0.f, 0.f, 0.f, 0.f);
    int j = 0;
    for (; j + 1 < nact; j += 2) {
        float w0 = __shfl_sync(FULL, cv, j);
        float w1 = __shfl_sync(FULL, cv, j + 1);
        int   i0 = __shfl_sync(FULL, ci, j);
        int   i1 = __shfl_sync(FULL, ci, j + 1);
        float4 q0 = __ldg(xb + ((unsigned)i0 << 5));
        float4 q1 = __ldg(xb + ((unsigned)i1 << 5));
        a0.x = fmaf(w0, q0.x, a0.x); a0.y = fmaf(w0, q0.y, a0.y);
        a0.z = fmaf(w0, q0.z, a0.z); a0.w = fmaf(w0, q0.w, a0.w);
        a1.x = fmaf(w1, q1.x, a1.x); a1.y = fmaf(w1, q1.y, a1.y);
        a1.z = fmaf(w1, q1.z, a1.z); a1.w = fmaf(w1, q1.w, a1.w);
    }
    if (j < nact) {                          // single tail
        float w0 = __shfl_sync(FULL, cv, j);
        int   i0 = __shfl_sync(FULL, ci, j);
        float4 q0 = __ldg(xb + ((unsigned)i0 << 5));
        a0.x = fmaf(w0, q0.x, a0.x); a0.y = fmaf(w0, q0.y, a0.y);
        a0.z = fmaf(w0, q0.z, a0.z); a0.w = fmaf(w0, q0.w, a0.w);
    }
    a0.x += a1.x; a0.y += a1.y; a0.z += a1.z; a0.w += a1.w;
    ((float4*)out)[(unsigned)c * 32u + (unsigned)lane] = a0;
}

extern "C" void kernel_launch(void* const* d_in, const int* in_sizes, int n_in,
                              void* d_out, int out_size)
{
    const float* params = (const float*)d_in[0];   // (262144, 3) f32
    const float* x      = (const float*)d_in[1];   // (65536, 128) f32
    float* out          = (float*)d_out;           // (65536, 128) f32
    (void)in_sizes; (void)n_in; (void)out_size;
    hyper_kernel<<<65536 / 8, 256>>>(params, x, out);
}